// round 15
// baseline (speedup 1.0000x reference)
#include <cuda_runtime.h>
#include <cuda_bf16.h>
#include <cstdint>
#include <math.h>

// ---------------- problem constants ----------------
#define Bsz   8
#define Hh    128
#define Wd    128
#define Cc    192
#define NHh   6
#define HD    32
#define LL    (Hh*Wd)     // 16384
#define TOK   (Bsz*LL)    // 131072
#define HDIMc 384
#define REDc  24
#define QKVN  576

// ---------------- scratch (device globals) ----------------
__device__ uint32_t g_n1  [(size_t)TOK*96];    // LN1 out, later LN2 out (bf16 packed)
__device__ uint32_t g_ao  [(size_t)TOK*96];    // attention concat-head output (bf16)
__device__ uint32_t g_qkv [(size_t)TOK*288];   // qkv bf16
__device__ uint32_t g_h   [(size_t)TOK*192];   // gelu(fc1) bf16
__device__ uint32_t g_h2  [(size_t)TOK*192];   // dwconv(h) bf16
__device__ uint32_t g_wt  [147456];            // transposed bf16 weights
__device__ uint32_t g_attn[(size_t)TOK*96];    // proj out (bf16 packed)
__device__ uint32_t g_conv[(size_t)TOK*96];    // gelu(dwconv(n1)) (bf16 packed)
__device__ float g_poolp[Bsz*128*Cc];
__device__ float g_cm  [Bsz*Cc];

#define WTB_QKV 0
#define WTB_PROJ 55296
#define WTB_FC1 73728
#define WTB_FC2 110592

__device__ __forceinline__ float gelu_f(float x){
    return 0.5f*x*(1.f + erff(x*0.70710678118654752f));
}
__device__ __forceinline__ uint32_t packbf(float lo, float hi){
    uint32_t r;
    asm("cvt.rn.bf16x2.f32 %0, %1, %2;" : "=r"(r) : "f"(hi), "f"(lo));
    return r;
}
__device__ __forceinline__ float2 unpackbf(uint32_t w){
    __nv_bfloat162 h = *reinterpret_cast<__nv_bfloat162*>(&w);
    float2 r; r.x = __bfloat162float(h.x); r.y = __bfloat162float(h.y);
    return r;
}
__device__ __forceinline__ void mma_bf16(float* c, uint32_t a0, uint32_t a1, uint32_t a2, uint32_t a3,
                                         uint32_t b0, uint32_t b1){
    asm volatile("mma.sync.aligned.m16n8k16.row.col.f32.bf16.bf16.f32 "
        "{%0,%1,%2,%3}, {%4,%5,%6,%7}, {%8,%9}, {%0,%1,%2,%3};"
        : "+f"(c[0]), "+f"(c[1]), "+f"(c[2]), "+f"(c[3])
        : "r"(a0), "r"(a1), "r"(a2), "r"(a3), "r"(b0), "r"(b1));
}
__device__ __forceinline__ void cpasync16(uint32_t saddr, const void* g){
    asm volatile("cp.async.ca.shared.global [%0], [%1], 16;" :: "r"(saddr), "l"(g));
}
__device__ __forceinline__ void ldm_x4(uint32_t* r, uint32_t saddr){
    asm volatile("ldmatrix.sync.aligned.m8n8.x4.shared.b16 {%0,%1,%2,%3}, [%4];"
        : "=r"(r[0]), "=r"(r[1]), "=r"(r[2]), "=r"(r[3]) : "r"(saddr));
}
__device__ __forceinline__ void ldm_x4_trans(uint32_t* r, uint32_t saddr){
    asm volatile("ldmatrix.sync.aligned.m8n8.x4.trans.shared.b16 {%0,%1,%2,%3}, [%4];"
        : "=r"(r[0]), "=r"(r[1]), "=r"(r[2]), "=r"(r[3]) : "r"(saddr));
}

// ---------------- weight transpose + bf16 pack (tiny) ----------------
__global__ void transpose_all(const float* __restrict__ qkvw, const float* __restrict__ projw,
                              const float* __restrict__ fc1w, const float* __restrict__ fc2w,
                              uint32_t* __restrict__ wt){
    int idx = blockIdx.x*256 + threadIdx.x;
    if (idx < 55296){
        int n = idx / 96, kp = idx % 96;
        wt[WTB_QKV + idx] = packbf(qkvw[(2*kp)*QKVN + n], qkvw[(2*kp+1)*QKVN + n]);
    } else if (idx < 73728){
        int l = idx - 55296; int n = l / 96, kp = l % 96;
        wt[idx] = packbf(projw[(2*kp)*Cc + n], projw[(2*kp+1)*Cc + n]);
    } else if (idx < 110592){
        int l = idx - 73728; int n = l / 96, kp = l % 96;
        wt[idx] = packbf(fc1w[(2*kp)*HDIMc + n], fc1w[(2*kp+1)*HDIMc + n]);
    } else if (idx < 147456){
        int l = idx - 110592; int n = l / 192, kp = l % 192;
        wt[idx] = packbf(fc2w[(2*kp)*Cc + n], fc2w[(2*kp+1)*Cc + n]);
    }
}

// ---------------- bf16 mma GEMM, cp.async 2-stage + ldmatrix ----------------
// C[M,N] = A[M,K] @ Bt[N,K]^T. A, Bt packed bf16 (K/2 words/row).
// BM=256, BN=64, BK=32; 8 warps (4m x 2n), warp tile 64x32.
// Loop order per iter: wait_group 0 -> barrier -> issue next stage -> compute.
// (wait must precede the barrier: cp.async completion is per-thread.)
// modes: 3 +residual(mat,f32 out), 4 bf16 out, 5 gelu+bf16 out, 6 +bias -> bf16 out
#define GRS 20
#define ASTAGE (256*GRS*4)
#define BSTAGE (64*GRS*4)
#define GEMM_SMEM (2*(ASTAGE + BSTAGE))   // 51200 B

__global__ __launch_bounds__(256) void gemm_mma(
    const uint32_t* __restrict__ A, const uint32_t* __restrict__ Bt,
    void* __restrict__ Cmat, const float* __restrict__ aux,
    int N, int K, int mode)
{
    extern __shared__ uint32_t gsm[];
    const int tid = threadIdx.x;
    const int wid = tid >> 5, lane = tid & 31;
    const int wm = wid >> 1, wn = wid & 1;
    const int lg = lane >> 2, lr = lane & 3;
    const int m0 = blockIdx.y << 8, n0 = blockIdx.x << 6;
    const int Kw = K >> 1;

    const uint32_t sBase = (uint32_t)__cvta_generic_to_shared(gsm);
    const uint32_t aBase = sBase;
    const uint32_t bBase = sBase + 2*ASTAGE;

    float acc[4][4][4] = {};

    // loaders: A = 1024 x 16B chunks (4/thread), B = 256 chunks (1/thread)
    const int raw = tid >> 2, oaw = (tid & 3) * 4;

    // ldmatrix per-warp byte offsets (within a stage)
    const int l16 = lane & 15, lh = lane >> 4;
    uint32_t aoffm[4];
    #pragma unroll
    for (int mt = 0; mt < 4; mt++)
        aoffm[mt] = ((wm*64 + mt*16 + l16)*GRS + lh*4)*4;
    const int b8 = lane & 7, sel = lane >> 3;
    uint32_t boffp[2];
    #pragma unroll
    for (int p = 0; p < 2; p++)
        boffp[p] = ((wn*32 + p*16 + (sel>>1)*8 + b8)*GRS + (sel&1)*4)*4;

    const int nIter = K >> 5;
    // prologue load (stage 0)
    {
        #pragma unroll
        for (int i = 0; i < 4; i++)
            cpasync16(aBase + ((raw + 64*i)*GRS + oaw)*4,
                      A + (size_t)(m0 + raw + 64*i)*Kw + oaw);
        cpasync16(bBase + (raw*GRS + oaw)*4, Bt + (size_t)(n0 + raw)*Kw + oaw);
        asm volatile("cp.async.commit_group;");
    }
    for (int it = 0; it < nIter; ++it){
        asm volatile("cp.async.wait_group 0;");   // this thread's pending copies done
        __syncthreads();                          // all threads' copies visible; prev compute done
        const int cur = it & 1;
        if (it + 1 < nIter){
            const int ns = cur ^ 1;
            const int k0w = (it+1) << 4;
            #pragma unroll
            for (int i = 0; i < 4; i++)
                cpasync16(aBase + ns*ASTAGE + ((raw + 64*i)*GRS + oaw)*4,
                          A + (size_t)(m0 + raw + 64*i)*Kw + k0w + oaw);
            cpasync16(bBase + ns*BSTAGE + (raw*GRS + oaw)*4,
                      Bt + (size_t)(n0 + raw)*Kw + k0w + oaw);
            asm volatile("cp.async.commit_group;");
        }
        const uint32_t aS = aBase + cur*ASTAGE, bS = bBase + cur*BSTAGE;
        #pragma unroll
        for (int kk = 0; kk < 2; kk++){
            uint32_t a[4][4], b[2][4];
            #pragma unroll
            for (int mt = 0; mt < 4; mt++)
                ldm_x4(a[mt], aS + aoffm[mt] + kk*32);
            ldm_x4(b[0], bS + boffp[0] + kk*32);
            ldm_x4(b[1], bS + boffp[1] + kk*32);
            #pragma unroll
            for (int mt = 0; mt < 4; mt++)
            #pragma unroll
            for (int nt = 0; nt < 4; nt++)
                mma_bf16(acc[mt][nt], a[mt][0], a[mt][1], a[mt][2], a[mt][3],
                         b[nt>>1][(nt&1)*2], b[nt>>1][(nt&1)*2+1]);
        }
    }
    // ---- epilogue ----
    #pragma unroll
    for (int mt = 0; mt < 4; mt++){
        #pragma unroll
        for (int rr = 0; rr < 2; rr++){
            int row = m0 + wm*64 + mt*16 + lg + rr*8;
            #pragma unroll
            for (int nt = 0; nt < 4; nt++){
                int col = n0 + wn*32 + nt*8 + lr*2;
                float d0 = acc[mt][nt][rr*2], d1 = acc[mt][nt][rr*2+1];
                size_t o = (size_t)row*N + col;
                if (mode == 3){
                    float2 rv = *(const float2*)&aux[o];
                    float2 v; v.x = d0 + rv.x; v.y = d1 + rv.y;
                    *(float2*)((float*)Cmat + o) = v;
                } else if (mode == 4){
                    ((uint32_t*)Cmat)[o >> 1] = packbf(d0, d1);
                } else if (mode == 5){
                    ((uint32_t*)Cmat)[o >> 1] = packbf(gelu_f(d0), gelu_f(d1));
                } else { // 6: +bias -> bf16
                    ((uint32_t*)Cmat)[o >> 1] = packbf(d0 + aux[col], d1 + aux[col+1]);
                }
            }
        }
    }
}

// ---------------- LayerNorm: one warp per token, bf16 packed out ----------------
__global__ void ln_kernel(const float* __restrict__ x, const float* __restrict__ w,
                          const float* __restrict__ b, uint32_t* __restrict__ out){
    int warp = (blockIdx.x*blockDim.x + threadIdx.x) >> 5;
    int lane = threadIdx.x & 31;
    if (warp >= TOK) return;
    const float* xp = x + (size_t)warp*Cc;
    float v[3][2]; float s = 0.f;
#pragma unroll
    for (int k=0;k<3;k++){
        float2 t = *(const float2*)&xp[2*(lane+32*k)];
        v[k][0]=t.x; v[k][1]=t.y; s += t.x + t.y;
    }
#pragma unroll
    for (int o=16;o;o>>=1) s += __shfl_xor_sync(0xffffffffu, s, o);
    float mean = s*(1.f/192.f);
    float q = 0.f;
#pragma unroll
    for (int k=0;k<3;k++){ float d0=v[k][0]-mean, d1=v[k][1]-mean; q += d0*d0 + d1*d1; }
#pragma unroll
    for (int o=16;o;o>>=1) q += __shfl_xor_sync(0xffffffffu, q, o);
    float inv = rsqrtf(q*(1.f/192.f)+1e-5f);
    uint32_t* op = out + (size_t)warp*96;
#pragma unroll
    for (int k=0;k<3;k++){
        int c2 = lane+32*k;
        float r0 = (v[k][0]-mean)*inv*w[2*c2]+b[2*c2];
        float r1 = (v[k][1]-mean)*inv*w[2*c2+1]+b[2*c2+1];
        op[c2] = packbf(r0, r1);
    }
}

// ---------------- mma window attention: block = (window, head-pair) ----------------
// q/k/v ALL token-major bf16 words (16 words per head per token, stride AQ_S).
// P@V uses ldmatrix.x4.trans on token-major V.
#define AQ_S 20

__global__ __launch_bounds__(256) void attn_mma(
    const uint32_t* __restrict__ qkv, const float* __restrict__ bias,
    uint32_t* __restrict__ ao)
{
    __shared__ uint32_t qs[2*64*AQ_S];
    __shared__ uint32_t ks[2*64*AQ_S];
    __shared__ uint32_t vs[2*64*AQ_S];

    const int win = blockIdx.x, hp = blockIdx.y;
    const int b = win >> 8, wh = (win>>4)&15, ww = win&15;
    const int h0 = hp*2;
    const int tid = threadIdx.x;
    const int wid = tid >> 5, lane = tid & 31;
    const int lg = lane >> 2, lr = lane & 3;

    // ---- fill: 4 lanes per token, identical word-store pattern for q,k,v ----
    {
        int t = tid >> 2, l4 = tid & 3;
        int lrow = wh*8 + (t>>3), lcol = ww*8 + (t&7);
        const uint32_t* src = qkv + ((size_t)b*LL + (size_t)lrow*Wd + lcol)*288;
        #pragma unroll
        for (int u = 0; u < 2; u++){
            int wofs = l4*8 + u*4;
            uint32_t vq[4], vk[4], vv[4];
            *(uint4*)vq = *(const uint4*)&src[h0*16 + wofs];
            *(uint4*)vk = *(const uint4*)&src[96 + h0*16 + wofs];
            *(uint4*)vv = *(const uint4*)&src[192 + h0*16 + wofs];
            #pragma unroll
            for (int i = 0; i < 4; i++){
                int w = wofs + i;
                int hh = w >> 4, wl = w & 15;
                qs[(hh*64 + t)*AQ_S + wl] = vq[i];
                ks[(hh*64 + t)*AQ_S + wl] = vk[i];
                vs[(hh*64 + t)*AQ_S + wl] = vv[i];
            }
        }
    }
    __syncthreads();

    const int h = wid >> 2, slab = wid & 3;
    const int r0 = slab*16 + lg, r1 = r0 + 8;
    const uint32_t* qsh = qs + h*64*AQ_S;
    const uint32_t* ksh = ks + h*64*AQ_S;
    const uint32_t vBase = (uint32_t)__cvta_generic_to_shared(vs);

    // S = Q @ K^T
    float s[8][4] = {};
    {
        const uint32_t* q0 = qsh + r0*AQ_S + lr;
        const uint32_t* q1 = q0 + 8*AQ_S;
        #pragma unroll
        for (int kk = 0; kk < 2; kk++){
            uint32_t a0 = q0[kk*8], a1 = q1[kk*8], a2 = q0[kk*8+4], a3 = q1[kk*8+4];
            #pragma unroll
            for (int nt = 0; nt < 8; nt++){
                const uint32_t* kr = ksh + (nt*8+lg)*AQ_S + kk*8 + lr;
                mma_bf16(s[nt], a0, a1, a2, a3, kr[0], kr[4]);
            }
        }
    }

    // scale + bias + softmax
    const float SC = 0.17677669529663687f;
    const float* bp = bias + (size_t)(h0+h)*4096;
    float m0 = -1e30f, m1 = -1e30f;
    #pragma unroll
    for (int nt = 0; nt < 8; nt++){
        float2 b0 = *(const float2*)&bp[r0*64 + nt*8 + 2*lr];
        float2 b1 = *(const float2*)&bp[r1*64 + nt*8 + 2*lr];
        s[nt][0] = s[nt][0]*SC + b0.x; s[nt][1] = s[nt][1]*SC + b0.y;
        s[nt][2] = s[nt][2]*SC + b1.x; s[nt][3] = s[nt][3]*SC + b1.y;
        m0 = fmaxf(m0, fmaxf(s[nt][0], s[nt][1]));
        m1 = fmaxf(m1, fmaxf(s[nt][2], s[nt][3]));
    }
    m0 = fmaxf(m0, __shfl_xor_sync(0xffffffffu, m0, 1));
    m0 = fmaxf(m0, __shfl_xor_sync(0xffffffffu, m0, 2));
    m1 = fmaxf(m1, __shfl_xor_sync(0xffffffffu, m1, 1));
    m1 = fmaxf(m1, __shfl_xor_sync(0xffffffffu, m1, 2));
    float s0 = 0.f, s1 = 0.f;
    #pragma unroll
    for (int nt = 0; nt < 8; nt++){
        s[nt][0] = __expf(s[nt][0]-m0); s[nt][1] = __expf(s[nt][1]-m0);
        s[nt][2] = __expf(s[nt][2]-m1); s[nt][3] = __expf(s[nt][3]-m1);
        s0 += s[nt][0] + s[nt][1];
        s1 += s[nt][2] + s[nt][3];
    }
    s0 += __shfl_xor_sync(0xffffffffu, s0, 1);
    s0 += __shfl_xor_sync(0xffffffffu, s0, 2);
    s1 += __shfl_xor_sync(0xffffffffu, s1, 1);
    s1 += __shfl_xor_sync(0xffffffffu, s1, 2);

    // O = P @ V  (B-fragments via transposed ldmatrix on token-major V)
    float o[4][4] = {};
    #pragma unroll
    for (int sp = 0; sp < 4; sp++){
        uint32_t a0 = packbf(s[2*sp][0],   s[2*sp][1]);
        uint32_t a1 = packbf(s[2*sp][2],   s[2*sp][3]);
        uint32_t a2 = packbf(s[2*sp+1][0], s[2*sp+1][1]);
        uint32_t a3 = packbf(s[2*sp+1][2], s[2*sp+1][3]);
        uint32_t va = vBase + (((h*64 + sp*16 + (lane & 15))*AQ_S) + (lane >> 4)*4)*4;
        uint32_t bv0[4], bv1[4];
        ldm_x4_trans(bv0, va);        // tiles: tok0-7/d0-7, tok8-15/d0-7, tok0-7/d8-15, tok8-15/d8-15
        ldm_x4_trans(bv1, va + 32);   // dims 16-31
        mma_bf16(o[0], a0, a1, a2, a3, bv0[0], bv0[1]);
        mma_bf16(o[1], a0, a1, a2, a3, bv0[2], bv0[3]);
        mma_bf16(o[2], a0, a1, a2, a3, bv1[0], bv1[1]);
        mma_bf16(o[3], a0, a1, a2, a3, bv1[2], bv1[3]);
    }
    float i0 = 1.f/s0, i1 = 1.f/s1;
    {
        int lrow = wh*8 + (r0>>3), lcol = ww*8 + (r0&7);
        uint32_t* op = ao + ((size_t)b*LL + (size_t)lrow*Wd + lcol)*96 + (h0+h)*16;
        #pragma unroll
        for (int nd = 0; nd < 4; nd++)
            op[nd*4 + lr] = packbf(o[nd][0]*i0, o[nd][1]*i0);
    }
    {
        int lrow = wh*8 + (r1>>3), lcol = ww*8 + (r1&7);
        uint32_t* op = ao + ((size_t)b*LL + (size_t)lrow*Wd + lcol)*96 + (h0+h)*16;
        #pragma unroll
        for (int nd = 0; nd < 4; nd++)
            op[nd*4 + lr] = packbf(o[nd][2]*i1, o[nd][3]*i1);
    }
}

// ---------------- depthwise 3x3 conv: 2 channels (1 word) x 4 pixels per thread ----------------
__global__ void dwconv4w(const uint32_t* __restrict__ in, const float* __restrict__ w9,
                         uint32_t* __restrict__ out, int Cw, int doGelu){
    long long idx = (long long)blockIdx.x*blockDim.x + threadIdx.x;
    long long total = (long long)TOK*Cw/4;
    if (idx >= total) return;
    int cw = (int)(idx % Cw);
    long long t = idx / Cw;
    int xq = (int)(t & 31);
    int y  = (int)((t >> 5) & 127);
    int b  = (int)(t >> 12);
    int x0 = xq*4;
    const uint32_t* base = in + (size_t)b*LL*Cw + cw;
    float r0[3][6], r1[3][6];
#pragma unroll
    for (int ky=0; ky<3; ky++){
        int iy = y + ky - 1;
        bool yok = (unsigned)iy < (unsigned)Hh;
#pragma unroll
        for (int kx=0; kx<6; kx++){
            int ix = x0 + kx - 1;
            bool ok = yok && ((unsigned)ix < (unsigned)Wd);
            if (ok){
                float2 p = unpackbf(base[((size_t)iy*Wd + ix)*Cw]);
                r0[ky][kx] = p.x; r1[ky][kx] = p.y;
            } else {
                r0[ky][kx] = 0.f; r1[ky][kx] = 0.f;
            }
        }
    }
    float wv0[9], wv1[9];
    const float* wp0 = w9 + (2*cw)*9;
#pragma unroll
    for (int k=0;k<9;k++){ wv0[k] = wp0[k]; wv1[k] = wp0[9+k]; }
    uint32_t* ob = out + ((size_t)b*LL + (size_t)y*Wd + x0)*Cw + cw;
#pragma unroll
    for (int xo=0; xo<4; xo++){
        float a0 = 0.f, a1 = 0.f;
#pragma unroll
        for (int ky=0;ky<3;ky++)
#pragma unroll
            for (int kx=0;kx<3;kx++){
                a0 += r0[ky][xo+kx]*wv0[ky*3+kx];
                a1 += r1[ky][xo+kx]*wv1[ky*3+kx];
            }
        if (doGelu){ a0 = gelu_f(a0); a1 = gelu_f(a1); }
        ob[(size_t)xo*Cw] = packbf(a0, a1);
    }
}

// ---------------- deterministic pooling + channel gate (bf16 conv in) ----------------
__global__ void pool_partial(const __nv_bfloat16* __restrict__ conv, float* __restrict__ pp){
    int b = blockIdx.y, chunk = blockIdx.x, c = threadIdx.x;
    const __nv_bfloat16* p = conv + ((size_t)b*LL + (size_t)chunk*128)*Cc + c;
    float s=0.f;
    for (int r=0;r<128;r++) s += __bfloat162float(p[(size_t)r*Cc]);
    pp[(b*128+chunk)*Cc + c] = s;
}

__global__ void pool_final_cm(const float* __restrict__ pp, const float* __restrict__ w1,
                              const float* __restrict__ w2, float* __restrict__ cm){
    int b = blockIdx.x, c = threadIdx.x;
    __shared__ float ps[Cc];
    __shared__ float ts[REDc];
    float s=0.f;
    for (int r=0;r<128;r++) s += pp[(b*128+r)*Cc + c];
    ps[c] = s*(1.f/(float)LL);
    __syncthreads();
    if (c < REDc){
        float t=0.f;
        for (int j=0;j<Cc;j++) t += ps[j]*w1[c*Cc+j];
        ts[c] = gelu_f(t);
    }
    __syncthreads();
    float a=0.f;
#pragma unroll
    for (int r=0;r<REDc;r++) a += ts[r]*w2[c*REDc+r];
    cm[b*Cc+c] = 1.f/(1.f+__expf(-a));
}

// ---------------- residual + LN2 fused: attn/conv bf16 in, xmid fp32, n2 bf16 ----------------
__global__ void resid_ln2_kernel(const float* __restrict__ x, const uint32_t* __restrict__ attn,
    const uint32_t* __restrict__ conv, const float* __restrict__ cm,
    const float* __restrict__ w, const float* __restrict__ bb,
    float* __restrict__ xmid, uint32_t* __restrict__ n2){
    int warp = (blockIdx.x*blockDim.x + threadIdx.x) >> 5;
    int lane = threadIdx.x & 31;
    if (warp >= TOK) return;
    int b = warp / LL;
    size_t base = (size_t)warp*Cc;
    float v[3][2]; float s=0.f;
#pragma unroll
    for (int k=0;k<3;k++){
        int c2 = lane+32*k;
        int c = 2*c2;
        float2 xv = *(const float2*)&x[base+c];
        float2 av = unpackbf(attn[(size_t)warp*96 + c2]);
        float2 cv = unpackbf(conv[(size_t)warp*96 + c2]);
        float2 gv = *(const float2*)&cm[b*Cc+c];
        float m0 = xv.x + av.x*gv.x + cv.x;
        float m1 = xv.y + av.y*gv.y + cv.y;
        float2 o; o.x=m0; o.y=m1;
        *(float2*)&xmid[base+c] = o;
        v[k][0]=m0; v[k][1]=m1; s+=m0+m1;
    }
#pragma unroll
    for (int o=16;o;o>>=1) s += __shfl_xor_sync(0xffffffffu, s, o);
    float mean = s*(1.f/192.f);
    float q = 0.f;
#pragma unroll
    for (int k=0;k<3;k++){ float d0=v[k][0]-mean, d1=v[k][1]-mean; q += d0*d0 + d1*d1; }
#pragma unroll
    for (int o=16;o;o>>=1) q += __shfl_xor_sync(0xffffffffu, q, o);
    float inv = rsqrtf(q*(1.f/192.f)+1e-5f);
    uint32_t* op = n2 + (size_t)warp*96;
#pragma unroll
    for (int k=0;k<3;k++){
        int c2 = lane+32*k;
        float r0 = (v[k][0]-mean)*inv*w[2*c2]+bb[2*c2];
        float r1 = (v[k][1]-mean)*inv*w[2*c2+1]+bb[2*c2+1];
        op[c2] = packbf(r0, r1);
    }
}

// ---------------- launch ----------------
extern "C" void kernel_launch(void* const* d_in, const int* in_sizes, int n_in,
                              void* d_out, int out_size){
    const float* x     = (const float*)d_in[0];
    const float* n1w   = (const float*)d_in[3];
    const float* n1b   = (const float*)d_in[4];
    const float* qkvw  = (const float*)d_in[5];
    const float* projw = (const float*)d_in[6];
    const float* projb = (const float*)d_in[7];
    const float* abias = (const float*)d_in[8];
    const float* convw = (const float*)d_in[9];
    const float* cgw1  = (const float*)d_in[10];
    const float* cgw2  = (const float*)d_in[11];
    const float* n2w   = (const float*)d_in[12];
    const float* n2b   = (const float*)d_in[13];
    const float* fc1w  = (const float*)d_in[14];
    const float* smixw = (const float*)d_in[15];
    const float* fc2w  = (const float*)d_in[16];
    float* out = (float*)d_out;

    uint32_t *n1p, *aop, *qkvp, *hp, *h2p, *wtp, *attnp, *convp;
    float *ppp, *cmp;
    cudaGetSymbolAddress((void**)&n1p,   g_n1);
    cudaGetSymbolAddress((void**)&aop,   g_ao);
    cudaGetSymbolAddress((void**)&qkvp,  g_qkv);
    cudaGetSymbolAddress((void**)&hp,    g_h);
    cudaGetSymbolAddress((void**)&h2p,   g_h2);
    cudaGetSymbolAddress((void**)&wtp,   g_wt);
    cudaGetSymbolAddress((void**)&attnp, g_attn);
    cudaGetSymbolAddress((void**)&convp, g_conv);
    cudaGetSymbolAddress((void**)&ppp,   g_poolp);
    cudaGetSymbolAddress((void**)&cmp,   g_cm);

    cudaFuncSetAttribute(gemm_mma, cudaFuncAttributeMaxDynamicSharedMemorySize, GEMM_SMEM);

    // 0. weight transposes -> bf16 (tiny)
    transpose_all<<<576, 256>>>(qkvw, projw, fc1w, fc2w, wtp);
    // 1. n1 = LN1(x) -> bf16
    ln_kernel<<<TOK/8, 256>>>(x, n1w, n1b, n1p);
    // 2. qkv = n1 @ qkv_w -> bf16
    gemm_mma<<<dim3(QKVN/64, TOK/256), 256, GEMM_SMEM>>>(n1p, wtp+WTB_QKV, qkvp, nullptr, QKVN, Cc, 4);
    // 3. attention -> ao (bf16)
    attn_mma<<<dim3(2048, 3), 256>>>(qkvp, abias, aop);
    // 4. attn_feat = ao @ proj_w + proj_b -> bf16
    gemm_mma<<<dim3(Cc/64, TOK/256), 256, GEMM_SMEM>>>(aop, wtp+WTB_PROJ, attnp, projb, Cc, Cc, 6);
    // 5. conv_feat = gelu(dwconv(n1)) -> bf16
    dwconv4w<<<(TOK*96/4 + 255)/256, 256>>>(n1p, convw, convp, 96, 1);
    // 6. channel gate
    pool_partial<<<dim3(128, Bsz), Cc>>>((const __nv_bfloat16*)convp, ppp);
    pool_final_cm<<<Bsz, Cc>>>(ppp, cgw1, cgw2, cmp);
    // 7. xmid -> out (fp32) ; n2 -> g_n1 (bf16, reuse)
    resid_ln2_kernel<<<TOK/8, 256>>>(x, attnp, convp, cmp, n2w, n2b, out, n1p);
    // 8. h = gelu(n2 @ fc1_w) -> bf16
    gemm_mma<<<dim3(HDIMc/64, TOK/256), 256, GEMM_SMEM>>>(n1p, wtp+WTB_FC1, hp, nullptr, HDIMc, Cc, 5);
    // 9. h2 = dwconv(h) -> bf16 (no gelu)
    dwconv4w<<<(TOK*192/4 + 255)/256, 256>>>(hp, smixw, h2p, 192, 0);
    // 10. out = xmid + h2 @ fc2_w (fp32 residual in-place)
    gemm_mma<<<dim3(Cc/64, TOK/256), 256, GEMM_SMEM>>>(h2p, wtp+WTB_FC2, out, out, Cc, HDIMc, 3);
}

// round 16
// speedup vs baseline: 1.0282x; 1.0282x over previous
#include <cuda_runtime.h>
#include <cuda_bf16.h>
#include <cstdint>
#include <math.h>

// ---------------- problem constants ----------------
#define Bsz   8
#define Hh    128
#define Wd    128
#define Cc    192
#define NHh   6
#define HD    32
#define LL    (Hh*Wd)     // 16384
#define TOK   (Bsz*LL)    // 131072
#define HDIMc 384
#define REDc  24
#define QKVN  576

// ---------------- scratch (device globals) ----------------
__device__ uint32_t g_n1  [(size_t)TOK*96];
__device__ uint32_t g_ao  [(size_t)TOK*96];
__device__ uint32_t g_qkv [(size_t)TOK*288];
__device__ uint32_t g_h   [(size_t)TOK*192];
__device__ uint32_t g_h2  [(size_t)TOK*192];
__device__ uint32_t g_wt  [147456];
__device__ uint32_t g_attn[(size_t)TOK*96];
__device__ uint32_t g_conv[(size_t)TOK*96];
__device__ float g_poolp[Bsz*128*Cc];
__device__ float g_cm  [Bsz*Cc];

#define WTB_QKV 0
#define WTB_PROJ 55296
#define WTB_FC1 73728
#define WTB_FC2 110592

__device__ __forceinline__ float gelu_f(float x){
    return 0.5f*x*(1.f + erff(x*0.70710678118654752f));
}
__device__ __forceinline__ uint32_t packbf(float lo, float hi){
    uint32_t r;
    asm("cvt.rn.bf16x2.f32 %0, %1, %2;" : "=r"(r) : "f"(hi), "f"(lo));
    return r;
}
__device__ __forceinline__ float2 unpackbf(uint32_t w){
    __nv_bfloat162 h = *reinterpret_cast<__nv_bfloat162*>(&w);
    float2 r; r.x = __bfloat162float(h.x); r.y = __bfloat162float(h.y);
    return r;
}
__device__ __forceinline__ void mma_bf16(float* c, uint32_t a0, uint32_t a1, uint32_t a2, uint32_t a3,
                                         uint32_t b0, uint32_t b1){
    asm volatile("mma.sync.aligned.m16n8k16.row.col.f32.bf16.bf16.f32 "
        "{%0,%1,%2,%3}, {%4,%5,%6,%7}, {%8,%9}, {%0,%1,%2,%3};"
        : "+f"(c[0]), "+f"(c[1]), "+f"(c[2]), "+f"(c[3])
        : "r"(a0), "r"(a1), "r"(a2), "r"(a3), "r"(b0), "r"(b1));
}
__device__ __forceinline__ void cpasync16(uint32_t saddr, const void* g){
    asm volatile("cp.async.ca.shared.global [%0], [%1], 16;" :: "r"(saddr), "l"(g));
}
__device__ __forceinline__ void ldm_x4(uint32_t* r, uint32_t saddr){
    asm volatile("ldmatrix.sync.aligned.m8n8.x4.shared.b16 {%0,%1,%2,%3}, [%4];"
        : "=r"(r[0]), "=r"(r[1]), "=r"(r[2]), "=r"(r[3]) : "r"(saddr));
}
__device__ __forceinline__ void ldm_x4_trans(uint32_t* r, uint32_t saddr){
    asm volatile("ldmatrix.sync.aligned.m8n8.x4.trans.shared.b16 {%0,%1,%2,%3}, [%4];"
        : "=r"(r[0]), "=r"(r[1]), "=r"(r[2]), "=r"(r[3]) : "r"(saddr));
}

// ---------------- weight transpose + bf16 pack (tiny) ----------------
__global__ void transpose_all(const float* __restrict__ qkvw, const float* __restrict__ projw,
                              const float* __restrict__ fc1w, const float* __restrict__ fc2w,
                              uint32_t* __restrict__ wt){
    int idx = blockIdx.x*256 + threadIdx.x;
    if (idx < 55296){
        int n = idx / 96, kp = idx % 96;
        wt[WTB_QKV + idx] = packbf(qkvw[(2*kp)*QKVN + n], qkvw[(2*kp+1)*QKVN + n]);
    } else if (idx < 73728){
        int l = idx - 55296; int n = l / 96, kp = l % 96;
        wt[idx] = packbf(projw[(2*kp)*Cc + n], projw[(2*kp+1)*Cc + n]);
    } else if (idx < 110592){
        int l = idx - 73728; int n = l / 96, kp = l % 96;
        wt[idx] = packbf(fc1w[(2*kp)*HDIMc + n], fc1w[(2*kp+1)*HDIMc + n]);
    } else if (idx < 147456){
        int l = idx - 110592; int n = l / 192, kp = l % 192;
        wt[idx] = packbf(fc2w[(2*kp)*Cc + n], fc2w[(2*kp+1)*Cc + n]);
    }
}

// ---------------- bf16 mma GEMM, cp.async 2-stage + ldmatrix ----------------
#define GRS 20
#define ASTAGE (256*GRS*4)
#define BSTAGE (64*GRS*4)
#define GEMM_SMEM (2*(ASTAGE + BSTAGE))   // 51200 B

__global__ __launch_bounds__(256) void gemm_mma(
    const uint32_t* __restrict__ A, const uint32_t* __restrict__ Bt,
    void* __restrict__ Cmat, const float* __restrict__ aux,
    int N, int K, int mode)
{
    extern __shared__ uint32_t gsm[];
    const int tid = threadIdx.x;
    const int wid = tid >> 5, lane = tid & 31;
    const int wm = wid >> 1, wn = wid & 1;
    const int lg = lane >> 2, lr = lane & 3;
    const int m0 = blockIdx.y << 8, n0 = blockIdx.x << 6;
    const int Kw = K >> 1;

    const uint32_t sBase = (uint32_t)__cvta_generic_to_shared(gsm);
    const uint32_t aBase = sBase;
    const uint32_t bBase = sBase + 2*ASTAGE;

    float acc[4][4][4] = {};

    const int raw = tid >> 2, oaw = (tid & 3) * 4;

    const int l16 = lane & 15, lh = lane >> 4;
    uint32_t aoffm[4];
    #pragma unroll
    for (int mt = 0; mt < 4; mt++)
        aoffm[mt] = ((wm*64 + mt*16 + l16)*GRS + lh*4)*4;
    const int b8 = lane & 7, sel = lane >> 3;
    uint32_t boffp[2];
    #pragma unroll
    for (int p = 0; p < 2; p++)
        boffp[p] = ((wn*32 + p*16 + (sel>>1)*8 + b8)*GRS + (sel&1)*4)*4;

    const int nIter = K >> 5;
    {
        #pragma unroll
        for (int i = 0; i < 4; i++)
            cpasync16(aBase + ((raw + 64*i)*GRS + oaw)*4,
                      A + (size_t)(m0 + raw + 64*i)*Kw + oaw);
        cpasync16(bBase + (raw*GRS + oaw)*4, Bt + (size_t)(n0 + raw)*Kw + oaw);
        asm volatile("cp.async.commit_group;");
    }
    for (int it = 0; it < nIter; ++it){
        asm volatile("cp.async.wait_group 0;");
        __syncthreads();
        const int cur = it & 1;
        if (it + 1 < nIter){
            const int ns = cur ^ 1;
            const int k0w = (it+1) << 4;
            #pragma unroll
            for (int i = 0; i < 4; i++)
                cpasync16(aBase + ns*ASTAGE + ((raw + 64*i)*GRS + oaw)*4,
                          A + (size_t)(m0 + raw + 64*i)*Kw + k0w + oaw);
            cpasync16(bBase + ns*BSTAGE + (raw*GRS + oaw)*4,
                      Bt + (size_t)(n0 + raw)*Kw + k0w + oaw);
            asm volatile("cp.async.commit_group;");
        }
        const uint32_t aS = aBase + cur*ASTAGE, bS = bBase + cur*BSTAGE;
        #pragma unroll
        for (int kk = 0; kk < 2; kk++){
            uint32_t a[4][4], b[2][4];
            #pragma unroll
            for (int mt = 0; mt < 4; mt++)
                ldm_x4(a[mt], aS + aoffm[mt] + kk*32);
            ldm_x4(b[0], bS + boffp[0] + kk*32);
            ldm_x4(b[1], bS + boffp[1] + kk*32);
            #pragma unroll
            for (int mt = 0; mt < 4; mt++)
            #pragma unroll
            for (int nt = 0; nt < 4; nt++)
                mma_bf16(acc[mt][nt], a[mt][0], a[mt][1], a[mt][2], a[mt][3],
                         b[nt>>1][(nt&1)*2], b[nt>>1][(nt&1)*2+1]);
        }
    }
    #pragma unroll
    for (int mt = 0; mt < 4; mt++){
        #pragma unroll
        for (int rr = 0; rr < 2; rr++){
            int row = m0 + wm*64 + mt*16 + lg + rr*8;
            #pragma unroll
            for (int nt = 0; nt < 4; nt++){
                int col = n0 + wn*32 + nt*8 + lr*2;
                float d0 = acc[mt][nt][rr*2], d1 = acc[mt][nt][rr*2+1];
                size_t o = (size_t)row*N + col;
                if (mode == 3){
                    float2 rv = *(const float2*)&aux[o];
                    float2 v; v.x = d0 + rv.x; v.y = d1 + rv.y;
                    *(float2*)((float*)Cmat + o) = v;
                } else if (mode == 4){
                    ((uint32_t*)Cmat)[o >> 1] = packbf(d0, d1);
                } else if (mode == 5){
                    ((uint32_t*)Cmat)[o >> 1] = packbf(gelu_f(d0), gelu_f(d1));
                } else { // 6: +bias -> bf16
                    ((uint32_t*)Cmat)[o >> 1] = packbf(d0 + aux[col], d1 + aux[col+1]);
                }
            }
        }
    }
}

// ---------------- LayerNorm: one warp per token, bf16 packed out ----------------
__global__ void ln_kernel(const float* __restrict__ x, const float* __restrict__ w,
                          const float* __restrict__ b, uint32_t* __restrict__ out){
    int warp = (blockIdx.x*blockDim.x + threadIdx.x) >> 5;
    int lane = threadIdx.x & 31;
    if (warp >= TOK) return;
    const float* xp = x + (size_t)warp*Cc;
    float v[3][2]; float s = 0.f;
#pragma unroll
    for (int k=0;k<3;k++){
        float2 t = *(const float2*)&xp[2*(lane+32*k)];
        v[k][0]=t.x; v[k][1]=t.y; s += t.x + t.y;
    }
#pragma unroll
    for (int o=16;o;o>>=1) s += __shfl_xor_sync(0xffffffffu, s, o);
    float mean = s*(1.f/192.f);
    float q = 0.f;
#pragma unroll
    for (int k=0;k<3;k++){ float d0=v[k][0]-mean, d1=v[k][1]-mean; q += d0*d0 + d1*d1; }
#pragma unroll
    for (int o=16;o;o>>=1) q += __shfl_xor_sync(0xffffffffu, q, o);
    float inv = rsqrtf(q*(1.f/192.f)+1e-5f);
    uint32_t* op = out + (size_t)warp*96;
#pragma unroll
    for (int k=0;k<3;k++){
        int c2 = lane+32*k;
        float r0 = (v[k][0]-mean)*inv*w[2*c2]+b[2*c2];
        float r1 = (v[k][1]-mean)*inv*w[2*c2+1]+b[2*c2+1];
        op[c2] = packbf(r0, r1);
    }
}

// ---------------- mma window attention: block = (window, head-pair) ----------------
// q/k/v token-major bf16 words. QK via ldmatrix(A)/ldmatrix(B); P@V via ldmatrix.trans.
#define AQ_S 20

__global__ __launch_bounds__(256) void attn_mma(
    const uint32_t* __restrict__ qkv, const float* __restrict__ bias,
    uint32_t* __restrict__ ao)
{
    __shared__ uint32_t qs[2*64*AQ_S];
    __shared__ uint32_t ks[2*64*AQ_S];
    __shared__ uint32_t vs[2*64*AQ_S];

    const int win = blockIdx.x, hp = blockIdx.y;
    const int b = win >> 8, wh = (win>>4)&15, ww = win&15;
    const int h0 = hp*2;
    const int tid = threadIdx.x;
    const int wid = tid >> 5, lane = tid & 31;
    const int lg = lane >> 2, lr = lane & 3;

    // ---- fill ----
    {
        int t = tid >> 2, l4 = tid & 3;
        int lrow = wh*8 + (t>>3), lcol = ww*8 + (t&7);
        const uint32_t* src = qkv + ((size_t)b*LL + (size_t)lrow*Wd + lcol)*288;
        #pragma unroll
        for (int u = 0; u < 2; u++){
            int wofs = l4*8 + u*4;
            uint32_t vq[4], vk[4], vv[4];
            *(uint4*)vq = *(const uint4*)&src[h0*16 + wofs];
            *(uint4*)vk = *(const uint4*)&src[96 + h0*16 + wofs];
            *(uint4*)vv = *(const uint4*)&src[192 + h0*16 + wofs];
            #pragma unroll
            for (int i = 0; i < 4; i++){
                int w = wofs + i;
                int hh = w >> 4, wl = w & 15;
                qs[(hh*64 + t)*AQ_S + wl] = vq[i];
                ks[(hh*64 + t)*AQ_S + wl] = vk[i];
                vs[(hh*64 + t)*AQ_S + wl] = vv[i];
            }
        }
    }
    __syncthreads();

    const int h = wid >> 2, slab = wid & 3;
    const int r0 = slab*16 + lg, r1 = r0 + 8;
    const uint32_t qBase = (uint32_t)__cvta_generic_to_shared(qs);
    const uint32_t kBase = (uint32_t)__cvta_generic_to_shared(ks);
    const uint32_t vBase = (uint32_t)__cvta_generic_to_shared(vs);

    // ldmatrix offsets
    const int l16 = lane & 15, lh = lane >> 4;
    const uint32_t qoff = ((h*64 + slab*16 + l16)*AQ_S + lh*4)*4;
    const int b8 = lane & 7, sel = lane >> 3;
    uint32_t koff[4];
    #pragma unroll
    for (int g = 0; g < 4; g++)
        koff[g] = ((h*64 + g*16 + (sel>>1)*8 + b8)*AQ_S + (sel&1)*4)*4;

    // S = Q @ K^T  (ldmatrix-fed)
    float s[8][4] = {};
    #pragma unroll
    for (int kk = 0; kk < 2; kk++){
        uint32_t aq[4];
        ldm_x4(aq, qBase + qoff + kk*32);
        #pragma unroll
        for (int g = 0; g < 4; g++){
            uint32_t bk[4];
            ldm_x4(bk, kBase + koff[g] + kk*32);
            mma_bf16(s[2*g],   aq[0], aq[1], aq[2], aq[3], bk[0], bk[1]);
            mma_bf16(s[2*g+1], aq[0], aq[1], aq[2], aq[3], bk[2], bk[3]);
        }
    }

    // scale + bias + softmax
    const float SC = 0.17677669529663687f;
    const float* bp = bias + (size_t)(h0+h)*4096;
    float m0 = -1e30f, m1 = -1e30f;
    #pragma unroll
    for (int nt = 0; nt < 8; nt++){
        float2 b0 = *(const float2*)&bp[r0*64 + nt*8 + 2*lr];
        float2 b1 = *(const float2*)&bp[r1*64 + nt*8 + 2*lr];
        s[nt][0] = s[nt][0]*SC + b0.x; s[nt][1] = s[nt][1]*SC + b0.y;
        s[nt][2] = s[nt][2]*SC + b1.x; s[nt][3] = s[nt][3]*SC + b1.y;
        m0 = fmaxf(m0, fmaxf(s[nt][0], s[nt][1]));
        m1 = fmaxf(m1, fmaxf(s[nt][2], s[nt][3]));
    }
    m0 = fmaxf(m0, __shfl_xor_sync(0xffffffffu, m0, 1));
    m0 = fmaxf(m0, __shfl_xor_sync(0xffffffffu, m0, 2));
    m1 = fmaxf(m1, __shfl_xor_sync(0xffffffffu, m1, 1));
    m1 = fmaxf(m1, __shfl_xor_sync(0xffffffffu, m1, 2));
    float s0 = 0.f, s1 = 0.f;
    #pragma unroll
    for (int nt = 0; nt < 8; nt++){
        s[nt][0] = __expf(s[nt][0]-m0); s[nt][1] = __expf(s[nt][1]-m0);
        s[nt][2] = __expf(s[nt][2]-m1); s[nt][3] = __expf(s[nt][3]-m1);
        s0 += s[nt][0] + s[nt][1];
        s1 += s[nt][2] + s[nt][3];
    }
    s0 += __shfl_xor_sync(0xffffffffu, s0, 1);
    s0 += __shfl_xor_sync(0xffffffffu, s0, 2);
    s1 += __shfl_xor_sync(0xffffffffu, s1, 1);
    s1 += __shfl_xor_sync(0xffffffffu, s1, 2);

    // O = P @ V
    float o[4][4] = {};
    #pragma unroll
    for (int sp = 0; sp < 4; sp++){
        uint32_t a0 = packbf(s[2*sp][0],   s[2*sp][1]);
        uint32_t a1 = packbf(s[2*sp][2],   s[2*sp][3]);
        uint32_t a2 = packbf(s[2*sp+1][0], s[2*sp+1][1]);
        uint32_t a3 = packbf(s[2*sp+1][2], s[2*sp+1][3]);
        uint32_t va = vBase + (((h*64 + sp*16 + l16)*AQ_S) + lh*4)*4;
        uint32_t bv0[4], bv1[4];
        ldm_x4_trans(bv0, va);
        ldm_x4_trans(bv1, va + 32);
        mma_bf16(o[0], a0, a1, a2, a3, bv0[0], bv0[1]);
        mma_bf16(o[1], a0, a1, a2, a3, bv0[2], bv0[3]);
        mma_bf16(o[2], a0, a1, a2, a3, bv1[0], bv1[1]);
        mma_bf16(o[3], a0, a1, a2, a3, bv1[2], bv1[3]);
    }
    float i0 = 1.f/s0, i1 = 1.f/s1;
    {
        int lrow = wh*8 + (r0>>3), lcol = ww*8 + (r0&7);
        uint32_t* op = ao + ((size_t)b*LL + (size_t)lrow*Wd + lcol)*96 + (h0+h)*16;
        #pragma unroll
        for (int nd = 0; nd < 4; nd++)
            op[nd*4 + lr] = packbf(o[nd][0]*i0, o[nd][1]*i0);
    }
    {
        int lrow = wh*8 + (r1>>3), lcol = ww*8 + (r1&7);
        uint32_t* op = ao + ((size_t)b*LL + (size_t)lrow*Wd + lcol)*96 + (h0+h)*16;
        #pragma unroll
        for (int nd = 0; nd < 4; nd++)
            op[nd*4 + lr] = packbf(o[nd][2]*i1, o[nd][3]*i1);
    }
}

// ---------------- depthwise 3x3 conv: 2 channels x 4 pixels per thread ----------------
__global__ void dwconv4w(const uint32_t* __restrict__ in, const float* __restrict__ w9,
                         uint32_t* __restrict__ out, int Cw, int doGelu){
    long long idx = (long long)blockIdx.x*blockDim.x + threadIdx.x;
    long long total = (long long)TOK*Cw/4;
    if (idx >= total) return;
    int cw = (int)(idx % Cw);
    long long t = idx / Cw;
    int xq = (int)(t & 31);
    int y  = (int)((t >> 5) & 127);
    int b  = (int)(t >> 12);
    int x0 = xq*4;
    const uint32_t* base = in + (size_t)b*LL*Cw + cw;
    float r0[3][6], r1[3][6];
#pragma unroll
    for (int ky=0; ky<3; ky++){
        int iy = y + ky - 1;
        bool yok = (unsigned)iy < (unsigned)Hh;
#pragma unroll
        for (int kx=0; kx<6; kx++){
            int ix = x0 + kx - 1;
            bool ok = yok && ((unsigned)ix < (unsigned)Wd);
            if (ok){
                float2 p = unpackbf(base[((size_t)iy*Wd + ix)*Cw]);
                r0[ky][kx] = p.x; r1[ky][kx] = p.y;
            } else {
                r0[ky][kx] = 0.f; r1[ky][kx] = 0.f;
            }
        }
    }
    float wv0[9], wv1[9];
    const float* wp0 = w9 + (2*cw)*9;
#pragma unroll
    for (int k=0;k<9;k++){ wv0[k] = wp0[k]; wv1[k] = wp0[9+k]; }
    uint32_t* ob = out + ((size_t)b*LL + (size_t)y*Wd + x0)*Cw + cw;
#pragma unroll
    for (int xo=0; xo<4; xo++){
        float a0 = 0.f, a1 = 0.f;
#pragma unroll
        for (int ky=0;ky<3;ky++)
#pragma unroll
            for (int kx=0;kx<3;kx++){
                a0 += r0[ky][xo+kx]*wv0[ky*3+kx];
                a1 += r1[ky][xo+kx]*wv1[ky*3+kx];
            }
        if (doGelu){ a0 = gelu_f(a0); a1 = gelu_f(a1); }
        ob[(size_t)xo*Cw] = packbf(a0, a1);
    }
}

// ---------------- deterministic pooling + channel gate ----------------
__global__ void pool_partial(const __nv_bfloat16* __restrict__ conv, float* __restrict__ pp){
    int b = blockIdx.y, chunk = blockIdx.x, c = threadIdx.x;
    const __nv_bfloat16* p = conv + ((size_t)b*LL + (size_t)chunk*128)*Cc + c;
    float s=0.f;
    for (int r=0;r<128;r++) s += __bfloat162float(p[(size_t)r*Cc]);
    pp[(b*128+chunk)*Cc + c] = s;
}

__global__ void pool_final_cm(const float* __restrict__ pp, const float* __restrict__ w1,
                              const float* __restrict__ w2, float* __restrict__ cm){
    int b = blockIdx.x, c = threadIdx.x;
    __shared__ float ps[Cc];
    __shared__ float ts[REDc];
    float s=0.f;
    for (int r=0;r<128;r++) s += pp[(b*128+r)*Cc + c];
    ps[c] = s*(1.f/(float)LL);
    __syncthreads();
    if (c < REDc){
        float t=0.f;
        for (int j=0;j<Cc;j++) t += ps[j]*w1[c*Cc+j];
        ts[c] = gelu_f(t);
    }
    __syncthreads();
    float a=0.f;
#pragma unroll
    for (int r=0;r<REDc;r++) a += ts[r]*w2[c*REDc+r];
    cm[b*Cc+c] = 1.f/(1.f+__expf(-a));
}

// ---------------- residual + LN2 fused ----------------
__global__ void resid_ln2_kernel(const float* __restrict__ x, const uint32_t* __restrict__ attn,
    const uint32_t* __restrict__ conv, const float* __restrict__ cm,
    const float* __restrict__ w, const float* __restrict__ bb,
    float* __restrict__ xmid, uint32_t* __restrict__ n2){
    int warp = (blockIdx.x*blockDim.x + threadIdx.x) >> 5;
    int lane = threadIdx.x & 31;
    if (warp >= TOK) return;
    int b = warp / LL;
    size_t base = (size_t)warp*Cc;
    float v[3][2]; float s=0.f;
#pragma unroll
    for (int k=0;k<3;k++){
        int c2 = lane+32*k;
        int c = 2*c2;
        float2 xv = *(const float2*)&x[base+c];
        float2 av = unpackbf(attn[(size_t)warp*96 + c2]);
        float2 cv = unpackbf(conv[(size_t)warp*96 + c2]);
        float2 gv = *(const float2*)&cm[b*Cc+c];
        float m0 = xv.x + av.x*gv.x + cv.x;
        float m1 = xv.y + av.y*gv.y + cv.y;
        float2 o; o.x=m0; o.y=m1;
        *(float2*)&xmid[base+c] = o;
        v[k][0]=m0; v[k][1]=m1; s+=m0+m1;
    }
#pragma unroll
    for (int o=16;o;o>>=1) s += __shfl_xor_sync(0xffffffffu, s, o);
    float mean = s*(1.f/192.f);
    float q = 0.f;
#pragma unroll
    for (int k=0;k<3;k++){ float d0=v[k][0]-mean, d1=v[k][1]-mean; q += d0*d0 + d1*d1; }
#pragma unroll
    for (int o=16;o;o>>=1) q += __shfl_xor_sync(0xffffffffu, q, o);
    float inv = rsqrtf(q*(1.f/192.f)+1e-5f);
    uint32_t* op = n2 + (size_t)warp*96;
#pragma unroll
    for (int k=0;k<3;k++){
        int c2 = lane+32*k;
        float r0 = (v[k][0]-mean)*inv*w[2*c2]+bb[2*c2];
        float r1 = (v[k][1]-mean)*inv*w[2*c2+1]+bb[2*c2+1];
        op[c2] = packbf(r0, r1);
    }
}

// ---------------- launch (multi-stream fork/join, graph-capturable) ----------------
extern "C" void kernel_launch(void* const* d_in, const int* in_sizes, int n_in,
                              void* d_out, int out_size){
    const float* x     = (const float*)d_in[0];
    const float* n1w   = (const float*)d_in[3];
    const float* n1b   = (const float*)d_in[4];
    const float* qkvw  = (const float*)d_in[5];
    const float* projw = (const float*)d_in[6];
    const float* projb = (const float*)d_in[7];
    const float* abias = (const float*)d_in[8];
    const float* convw = (const float*)d_in[9];
    const float* cgw1  = (const float*)d_in[10];
    const float* cgw2  = (const float*)d_in[11];
    const float* n2w   = (const float*)d_in[12];
    const float* n2b   = (const float*)d_in[13];
    const float* fc1w  = (const float*)d_in[14];
    const float* smixw = (const float*)d_in[15];
    const float* fc2w  = (const float*)d_in[16];
    float* out = (float*)d_out;

    uint32_t *n1p, *aop, *qkvp, *hp, *h2p, *wtp, *attnp, *convp;
    float *ppp, *cmp;
    cudaGetSymbolAddress((void**)&n1p,   g_n1);
    cudaGetSymbolAddress((void**)&aop,   g_ao);
    cudaGetSymbolAddress((void**)&qkvp,  g_qkv);
    cudaGetSymbolAddress((void**)&hp,    g_h);
    cudaGetSymbolAddress((void**)&h2p,   g_h2);
    cudaGetSymbolAddress((void**)&wtp,   g_wt);
    cudaGetSymbolAddress((void**)&attnp, g_attn);
    cudaGetSymbolAddress((void**)&convp, g_conv);
    cudaGetSymbolAddress((void**)&ppp,   g_poolp);
    cudaGetSymbolAddress((void**)&cmp,   g_cm);

    cudaFuncSetAttribute(gemm_mma, cudaFuncAttributeMaxDynamicSharedMemorySize, GEMM_SMEM);

    // one-time resources (created before first capture; objects only, no device memory)
    static cudaStream_t s1 = nullptr;
    static cudaEvent_t evRoot = nullptr, evT = nullptr, evLN = nullptr, evCM = nullptr;
    if (s1 == nullptr){
        cudaStreamCreateWithFlags(&s1, cudaStreamNonBlocking);
        cudaEventCreateWithFlags(&evRoot, cudaEventDisableTiming);
        cudaEventCreateWithFlags(&evT,    cudaEventDisableTiming);
        cudaEventCreateWithFlags(&evLN,   cudaEventDisableTiming);
        cudaEventCreateWithFlags(&evCM,   cudaEventDisableTiming);
    }

    // fork side stream from capture origin
    cudaEventRecord(evRoot, 0);
    cudaStreamWaitEvent(s1, evRoot, 0);

    // s1: weight transpose (independent of LN)
    transpose_all<<<576, 256, 0, s1>>>(qkvw, projw, fc1w, fc2w, wtp);
    cudaEventRecord(evT, s1);

    // main: LN1
    ln_kernel<<<TOK/8, 256>>>(x, n1w, n1b, n1p);
    cudaEventRecord(evLN, 0);

    // s1: conv-gate chain (needs n1)
    cudaStreamWaitEvent(s1, evLN, 0);
    dwconv4w<<<(TOK*96/4 + 255)/256, 256, 0, s1>>>(n1p, convw, convp, 96, 1);
    pool_partial<<<dim3(128, Bsz), Cc, 0, s1>>>((const __nv_bfloat16*)convp, ppp);
    pool_final_cm<<<Bsz, Cc, 0, s1>>>(ppp, cgw1, cgw2, cmp);
    cudaEventRecord(evCM, s1);

    // main: qkv (needs wt) -> attn -> proj
    cudaStreamWaitEvent(0, evT, 0);
    gemm_mma<<<dim3(QKVN/64, TOK/256), 256, GEMM_SMEM>>>(n1p, wtp+WTB_QKV, qkvp, nullptr, QKVN, Cc, 4);
    attn_mma<<<dim3(2048, 3), 256>>>(qkvp, abias, aop);
    gemm_mma<<<dim3(Cc/64, TOK/256), 256, GEMM_SMEM>>>(aop, wtp+WTB_PROJ, attnp, projb, Cc, Cc, 6);

    // join, then serial FFN chain
    cudaStreamWaitEvent(0, evCM, 0);
    resid_ln2_kernel<<<TOK/8, 256>>>(x, attnp, convp, cmp, n2w, n2b, out, n1p);
    gemm_mma<<<dim3(HDIMc/64, TOK/256), 256, GEMM_SMEM>>>(n1p, wtp+WTB_FC1, hp, nullptr, HDIMc, Cc, 5);
    dwconv4w<<<(TOK*192/4 + 255)/256, 256>>>(hp, smixw, h2p, 192, 0);
    gemm_mma<<<dim3(Cc/64, TOK/256), 256, GEMM_SMEM>>>(h2p, wtp+WTB_FC2, out, out, Cc, HDIMc, 3);
}

// round 17
// speedup vs baseline: 1.0294x; 1.0012x over previous
#include <cuda_runtime.h>
#include <cuda_bf16.h>
#include <cstdint>
#include <math.h>

// ---------------- problem constants ----------------
#define Bsz   8
#define Hh    128
#define Wd    128
#define Cc    192
#define NHh   6
#define HD    32
#define LL    (Hh*Wd)     // 16384
#define TOK   (Bsz*LL)    // 131072
#define HDIMc 384
#define REDc  24
#define QKVN  576

// ---------------- scratch (device globals) ----------------
__device__ uint32_t g_n1  [(size_t)TOK*96];
__device__ uint32_t g_ao  [(size_t)TOK*96];
__device__ uint32_t g_qkv [(size_t)TOK*288];   // WINDOW-MAJOR token order
__device__ uint32_t g_h   [(size_t)TOK*192];
__device__ uint32_t g_h2  [(size_t)TOK*192];
__device__ uint32_t g_wt  [147456];
__device__ uint32_t g_attn[(size_t)TOK*96];
__device__ uint32_t g_conv[(size_t)TOK*96];
__device__ float g_poolp[Bsz*128*Cc];
__device__ float g_cm  [Bsz*Cc];

#define WTB_QKV 0
#define WTB_PROJ 55296
#define WTB_FC1 73728
#define WTB_FC2 110592

__device__ __forceinline__ float gelu_f(float x){
    return 0.5f*x*(1.f + erff(x*0.70710678118654752f));
}
__device__ __forceinline__ uint32_t packbf(float lo, float hi){
    uint32_t r;
    asm("cvt.rn.bf16x2.f32 %0, %1, %2;" : "=r"(r) : "f"(hi), "f"(lo));
    return r;
}
__device__ __forceinline__ float2 unpackbf(uint32_t w){
    __nv_bfloat162 h = *reinterpret_cast<__nv_bfloat162*>(&w);
    float2 r; r.x = __bfloat162float(h.x); r.y = __bfloat162float(h.y);
    return r;
}
__device__ __forceinline__ void mma_bf16(float* c, uint32_t a0, uint32_t a1, uint32_t a2, uint32_t a3,
                                         uint32_t b0, uint32_t b1){
    asm volatile("mma.sync.aligned.m16n8k16.row.col.f32.bf16.bf16.f32 "
        "{%0,%1,%2,%3}, {%4,%5,%6,%7}, {%8,%9}, {%0,%1,%2,%3};"
        : "+f"(c[0]), "+f"(c[1]), "+f"(c[2]), "+f"(c[3])
        : "r"(a0), "r"(a1), "r"(a2), "r"(a3), "r"(b0), "r"(b1));
}
__device__ __forceinline__ void cpasync16(uint32_t saddr, const void* g){
    asm volatile("cp.async.ca.shared.global [%0], [%1], 16;" :: "r"(saddr), "l"(g));
}
__device__ __forceinline__ void ldm_x4(uint32_t* r, uint32_t saddr){
    asm volatile("ldmatrix.sync.aligned.m8n8.x4.shared.b16 {%0,%1,%2,%3}, [%4];"
        : "=r"(r[0]), "=r"(r[1]), "=r"(r[2]), "=r"(r[3]) : "r"(saddr));
}
__device__ __forceinline__ void ldm_x4_trans(uint32_t* r, uint32_t saddr){
    asm volatile("ldmatrix.sync.aligned.m8n8.x4.trans.shared.b16 {%0,%1,%2,%3}, [%4];"
        : "=r"(r[0]), "=r"(r[1]), "=r"(r[2]), "=r"(r[3]) : "r"(saddr));
}

// ---------------- weight transpose + bf16 pack (tiny) ----------------
__global__ void transpose_all(const float* __restrict__ qkvw, const float* __restrict__ projw,
                              const float* __restrict__ fc1w, const float* __restrict__ fc2w,
                              uint32_t* __restrict__ wt){
    int idx = blockIdx.x*256 + threadIdx.x;
    if (idx < 55296){
        int n = idx / 96, kp = idx % 96;
        wt[WTB_QKV + idx] = packbf(qkvw[(2*kp)*QKVN + n], qkvw[(2*kp+1)*QKVN + n]);
    } else if (idx < 73728){
        int l = idx - 55296; int n = l / 96, kp = l % 96;
        wt[idx] = packbf(projw[(2*kp)*Cc + n], projw[(2*kp+1)*Cc + n]);
    } else if (idx < 110592){
        int l = idx - 73728; int n = l / 96, kp = l % 96;
        wt[idx] = packbf(fc1w[(2*kp)*HDIMc + n], fc1w[(2*kp+1)*HDIMc + n]);
    } else if (idx < 147456){
        int l = idx - 110592; int n = l / 192, kp = l % 192;
        wt[idx] = packbf(fc2w[(2*kp)*Cc + n], fc2w[(2*kp+1)*Cc + n]);
    }
}

// ---------------- bf16 mma GEMM, cp.async 3-stage + ldmatrix ----------------
// modes: 3 +residual(mat,f32 out), 4 bf16 out, 5 gelu+bf16 out, 6 +bias->bf16,
//        7 bf16 out with window-major row permutation (qkv)
#define GRS 20
#define ASTAGE (256*GRS*4)
#define BSTAGE (64*GRS*4)
#define NSTG 3
#define GEMM_SMEM (NSTG*(ASTAGE + BSTAGE))   // 76800 B

__global__ __launch_bounds__(256) void gemm_mma(
    const uint32_t* __restrict__ A, const uint32_t* __restrict__ Bt,
    void* __restrict__ Cmat, const float* __restrict__ aux,
    int N, int K, int mode)
{
    extern __shared__ uint32_t gsm[];
    const int tid = threadIdx.x;
    const int wid = tid >> 5, lane = tid & 31;
    const int wm = wid >> 1, wn = wid & 1;
    const int lg = lane >> 2, lr = lane & 3;
    const int m0 = blockIdx.y << 8, n0 = blockIdx.x << 6;
    const int Kw = K >> 1;

    const uint32_t sBase = (uint32_t)__cvta_generic_to_shared(gsm);
    const uint32_t aBase = sBase;
    const uint32_t bBase = sBase + NSTG*ASTAGE;

    float acc[4][4][4] = {};

    const int raw = tid >> 2, oaw = (tid & 3) * 4;

    const int l16 = lane & 15, lh = lane >> 4;
    uint32_t aoffm[4];
    #pragma unroll
    for (int mt = 0; mt < 4; mt++)
        aoffm[mt] = ((wm*64 + mt*16 + l16)*GRS + lh*4)*4;
    const int b8 = lane & 7, sel = lane >> 3;
    uint32_t boffp[2];
    #pragma unroll
    for (int p = 0; p < 2; p++)
        boffp[p] = ((wn*32 + p*16 + (sel>>1)*8 + b8)*GRS + (sel&1)*4)*4;

    const int nIter = K >> 5;
    // prologue: load stages 0 and 1
    #pragma unroll
    for (int s = 0; s < 2; s++){
        const int k0w = s << 4;
        #pragma unroll
        for (int i = 0; i < 4; i++)
            cpasync16(aBase + s*ASTAGE + ((raw + 64*i)*GRS + oaw)*4,
                      A + (size_t)(m0 + raw + 64*i)*Kw + k0w + oaw);
        cpasync16(bBase + s*BSTAGE + (raw*GRS + oaw)*4,
                  Bt + (size_t)(n0 + raw)*Kw + k0w + oaw);
        asm volatile("cp.async.commit_group;");
    }
    for (int it = 0; it < nIter; ++it){
        if (it + 1 < nIter) asm volatile("cp.async.wait_group 1;");
        else                asm volatile("cp.async.wait_group 0;");
        __syncthreads();
        if (it + 2 < nIter){
            const int ns = (it + 2) % NSTG;
            const int k0w = (it+2) << 4;
            #pragma unroll
            for (int i = 0; i < 4; i++)
                cpasync16(aBase + ns*ASTAGE + ((raw + 64*i)*GRS + oaw)*4,
                          A + (size_t)(m0 + raw + 64*i)*Kw + k0w + oaw);
            cpasync16(bBase + ns*BSTAGE + (raw*GRS + oaw)*4,
                      Bt + (size_t)(n0 + raw)*Kw + k0w + oaw);
            asm volatile("cp.async.commit_group;");
        }
        const int cur = it % NSTG;
        const uint32_t aS = aBase + cur*ASTAGE, bS = bBase + cur*BSTAGE;
        #pragma unroll
        for (int kk = 0; kk < 2; kk++){
            uint32_t a[4][4], b[2][4];
            #pragma unroll
            for (int mt = 0; mt < 4; mt++)
                ldm_x4(a[mt], aS + aoffm[mt] + kk*32);
            ldm_x4(b[0], bS + boffp[0] + kk*32);
            ldm_x4(b[1], bS + boffp[1] + kk*32);
            #pragma unroll
            for (int mt = 0; mt < 4; mt++)
            #pragma unroll
            for (int nt = 0; nt < 4; nt++)
                mma_bf16(acc[mt][nt], a[mt][0], a[mt][1], a[mt][2], a[mt][3],
                         b[nt>>1][(nt&1)*2], b[nt>>1][(nt&1)*2+1]);
        }
    }
    // ---- epilogue ----
    #pragma unroll
    for (int mt = 0; mt < 4; mt++){
        #pragma unroll
        for (int rr = 0; rr < 2; rr++){
            int row = m0 + wm*64 + mt*16 + lg + rr*8;
            int prow = row;
            if (mode == 7){
                int bb2 = row >> 14, rem = row & 16383;
                int y = rem >> 7, xx = rem & 127;
                prow = (((bb2 << 8) | ((y >> 3) << 4) | (xx >> 3)) << 6)
                       | (((y & 7) << 3) | (xx & 7));
            }
            #pragma unroll
            for (int nt = 0; nt < 4; nt++){
                int col = n0 + wn*32 + nt*8 + lr*2;
                float d0 = acc[mt][nt][rr*2], d1 = acc[mt][nt][rr*2+1];
                size_t o = (size_t)prow*N + col;
                if (mode == 3){
                    float2 rv = *(const float2*)&aux[o];
                    float2 v; v.x = d0 + rv.x; v.y = d1 + rv.y;
                    *(float2*)((float*)Cmat + o) = v;
                } else if (mode == 4 || mode == 7){
                    ((uint32_t*)Cmat)[o >> 1] = packbf(d0, d1);
                } else if (mode == 5){
                    ((uint32_t*)Cmat)[o >> 1] = packbf(gelu_f(d0), gelu_f(d1));
                } else { // 6: +bias -> bf16
                    ((uint32_t*)Cmat)[o >> 1] = packbf(d0 + aux[col], d1 + aux[col+1]);
                }
            }
        }
    }
}

// ---------------- LayerNorm: one warp per token, bf16 packed out ----------------
__global__ void ln_kernel(const float* __restrict__ x, const float* __restrict__ w,
                          const float* __restrict__ b, uint32_t* __restrict__ out){
    int warp = (blockIdx.x*blockDim.x + threadIdx.x) >> 5;
    int lane = threadIdx.x & 31;
    if (warp >= TOK) return;
    const float* xp = x + (size_t)warp*Cc;
    float v[3][2]; float s = 0.f;
#pragma unroll
    for (int k=0;k<3;k++){
        float2 t = *(const float2*)&xp[2*(lane+32*k)];
        v[k][0]=t.x; v[k][1]=t.y; s += t.x + t.y;
    }
#pragma unroll
    for (int o=16;o;o>>=1) s += __shfl_xor_sync(0xffffffffu, s, o);
    float mean = s*(1.f/192.f);
    float q = 0.f;
#pragma unroll
    for (int k=0;k<3;k++){ float d0=v[k][0]-mean, d1=v[k][1]-mean; q += d0*d0 + d1*d1; }
#pragma unroll
    for (int o=16;o;o>>=1) q += __shfl_xor_sync(0xffffffffu, q, o);
    float inv = rsqrtf(q*(1.f/192.f)+1e-5f);
    uint32_t* op = out + (size_t)warp*96;
#pragma unroll
    for (int k=0;k<3;k++){
        int c2 = lane+32*k;
        float r0 = (v[k][0]-mean)*inv*w[2*c2]+b[2*c2];
        float r1 = (v[k][1]-mean)*inv*w[2*c2+1]+b[2*c2+1];
        op[c2] = packbf(r0, r1);
    }
}

// ---------------- mma window attention: block = (window, head-pair) ----------------
// qkv is WINDOW-MAJOR: window win's 64 tokens contiguous (288 words each).
#define AQ_S 20

__global__ __launch_bounds__(256) void attn_mma(
    const uint32_t* __restrict__ qkv, const float* __restrict__ bias,
    uint32_t* __restrict__ ao)
{
    __shared__ uint32_t qs[2*64*AQ_S];
    __shared__ uint32_t ks[2*64*AQ_S];
    __shared__ uint32_t vs[2*64*AQ_S];

    const int win = blockIdx.x, hp = blockIdx.y;
    const int b = win >> 8, wh = (win>>4)&15, ww = win&15;
    const int h0 = hp*2;
    const int tid = threadIdx.x;
    const int wid = tid >> 5, lane = tid & 31;
    const int lg = lane >> 2, lr = lane & 3;

    // ---- fill: contiguous window block, uint4 loads AND uint4 smem stores ----
    {
        int t = tid >> 2, l4 = tid & 3;
        const uint32_t* src = qkv + ((size_t)win*64 + t)*288;
        #pragma unroll
        for (int u = 0; u < 2; u++){
            int wofs = l4*8 + u*4;
            int hh = wofs >> 4, wl0 = wofs & 15;
            int rowo = (hh*64 + t)*AQ_S + wl0;
            uint4 vq = *(const uint4*)&src[h0*16 + wofs];
            uint4 vk = *(const uint4*)&src[96 + h0*16 + wofs];
            uint4 vv = *(const uint4*)&src[192 + h0*16 + wofs];
            *(uint4*)&qs[rowo] = vq;
            *(uint4*)&ks[rowo] = vk;
            *(uint4*)&vs[rowo] = vv;
        }
    }
    __syncthreads();

    const int h = wid >> 2, slab = wid & 3;
    const int r0 = slab*16 + lg, r1 = r0 + 8;
    const uint32_t qBase = (uint32_t)__cvta_generic_to_shared(qs);
    const uint32_t kBase = (uint32_t)__cvta_generic_to_shared(ks);
    const uint32_t vBase = (uint32_t)__cvta_generic_to_shared(vs);

    const int l16 = lane & 15, lh = lane >> 4;
    const uint32_t qoff = ((h*64 + slab*16 + l16)*AQ_S + lh*4)*4;
    const int b8 = lane & 7, sel = lane >> 3;
    uint32_t koff[4];
    #pragma unroll
    for (int g = 0; g < 4; g++)
        koff[g] = ((h*64 + g*16 + (sel>>1)*8 + b8)*AQ_S + (sel&1)*4)*4;

    // S = Q @ K^T
    float s[8][4] = {};
    #pragma unroll
    for (int kk = 0; kk < 2; kk++){
        uint32_t aq[4];
        ldm_x4(aq, qBase + qoff + kk*32);
        #pragma unroll
        for (int g = 0; g < 4; g++){
            uint32_t bk[4];
            ldm_x4(bk, kBase + koff[g] + kk*32);
            mma_bf16(s[2*g],   aq[0], aq[1], aq[2], aq[3], bk[0], bk[1]);
            mma_bf16(s[2*g+1], aq[0], aq[1], aq[2], aq[3], bk[2], bk[3]);
        }
    }

    // scale + bias + softmax
    const float SC = 0.17677669529663687f;
    const float* bp = bias + (size_t)(h0+h)*4096;
    float m0 = -1e30f, m1 = -1e30f;
    #pragma unroll
    for (int nt = 0; nt < 8; nt++){
        float2 b0 = *(const float2*)&bp[r0*64 + nt*8 + 2*lr];
        float2 b1 = *(const float2*)&bp[r1*64 + nt*8 + 2*lr];
        s[nt][0] = s[nt][0]*SC + b0.x; s[nt][1] = s[nt][1]*SC + b0.y;
        s[nt][2] = s[nt][2]*SC + b1.x; s[nt][3] = s[nt][3]*SC + b1.y;
        m0 = fmaxf(m0, fmaxf(s[nt][0], s[nt][1]));
        m1 = fmaxf(m1, fmaxf(s[nt][2], s[nt][3]));
    }
    m0 = fmaxf(m0, __shfl_xor_sync(0xffffffffu, m0, 1));
    m0 = fmaxf(m0, __shfl_xor_sync(0xffffffffu, m0, 2));
    m1 = fmaxf(m1, __shfl_xor_sync(0xffffffffu, m1, 1));
    m1 = fmaxf(m1, __shfl_xor_sync(0xffffffffu, m1, 2));
    float s0 = 0.f, s1 = 0.f;
    #pragma unroll
    for (int nt = 0; nt < 8; nt++){
        s[nt][0] = __expf(s[nt][0]-m0); s[nt][1] = __expf(s[nt][1]-m0);
        s[nt][2] = __expf(s[nt][2]-m1); s[nt][3] = __expf(s[nt][3]-m1);
        s0 += s[nt][0] + s[nt][1];
        s1 += s[nt][2] + s[nt][3];
    }
    s0 += __shfl_xor_sync(0xffffffffu, s0, 1);
    s0 += __shfl_xor_sync(0xffffffffu, s0, 2);
    s1 += __shfl_xor_sync(0xffffffffu, s1, 1);
    s1 += __shfl_xor_sync(0xffffffffu, s1, 2);

    // O = P @ V
    float o[4][4] = {};
    #pragma unroll
    for (int sp = 0; sp < 4; sp++){
        uint32_t a0 = packbf(s[2*sp][0],   s[2*sp][1]);
        uint32_t a1 = packbf(s[2*sp][2],   s[2*sp][3]);
        uint32_t a2 = packbf(s[2*sp+1][0], s[2*sp+1][1]);
        uint32_t a3 = packbf(s[2*sp+1][2], s[2*sp+1][3]);
        uint32_t va = vBase + (((h*64 + sp*16 + l16)*AQ_S) + lh*4)*4;
        uint32_t bv0[4], bv1[4];
        ldm_x4_trans(bv0, va);
        ldm_x4_trans(bv1, va + 32);
        mma_bf16(o[0], a0, a1, a2, a3, bv0[0], bv0[1]);
        mma_bf16(o[1], a0, a1, a2, a3, bv0[2], bv0[3]);
        mma_bf16(o[2], a0, a1, a2, a3, bv1[0], bv1[1]);
        mma_bf16(o[3], a0, a1, a2, a3, bv1[2], bv1[3]);
    }
    float i0 = 1.f/s0, i1 = 1.f/s1;
    {
        int lrow = wh*8 + (r0>>3), lcol = ww*8 + (r0&7);
        uint32_t* op = ao + ((size_t)b*LL + (size_t)lrow*Wd + lcol)*96 + (h0+h)*16;
        #pragma unroll
        for (int nd = 0; nd < 4; nd++)
            op[nd*4 + lr] = packbf(o[nd][0]*i0, o[nd][1]*i0);
    }
    {
        int lrow = wh*8 + (r1>>3), lcol = ww*8 + (r1&7);
        uint32_t* op = ao + ((size_t)b*LL + (size_t)lrow*Wd + lcol)*96 + (h0+h)*16;
        #pragma unroll
        for (int nd = 0; nd < 4; nd++)
            op[nd*4 + lr] = packbf(o[nd][2]*i1, o[nd][3]*i1);
    }
}

// ---------------- depthwise 3x3 conv: 2 channels x 4 pixels per thread ----------------
__global__ void dwconv4w(const uint32_t* __restrict__ in, const float* __restrict__ w9,
                         uint32_t* __restrict__ out, int Cw, int doGelu){
    long long idx = (long long)blockIdx.x*blockDim.x + threadIdx.x;
    long long total = (long long)TOK*Cw/4;
    if (idx >= total) return;
    int cw = (int)(idx % Cw);
    long long t = idx / Cw;
    int xq = (int)(t & 31);
    int y  = (int)((t >> 5) & 127);
    int b  = (int)(t >> 12);
    int x0 = xq*4;
    const uint32_t* base = in + (size_t)b*LL*Cw + cw;
    float r0[3][6], r1[3][6];
#pragma unroll
    for (int ky=0; ky<3; ky++){
        int iy = y + ky - 1;
        bool yok = (unsigned)iy < (unsigned)Hh;
#pragma unroll
        for (int kx=0; kx<6; kx++){
            int ix = x0 + kx - 1;
            bool ok = yok && ((unsigned)ix < (unsigned)Wd);
            if (ok){
                float2 p = unpackbf(base[((size_t)iy*Wd + ix)*Cw]);
                r0[ky][kx] = p.x; r1[ky][kx] = p.y;
            } else {
                r0[ky][kx] = 0.f; r1[ky][kx] = 0.f;
            }
        }
    }
    float wv0[9], wv1[9];
    const float* wp0 = w9 + (2*cw)*9;
#pragma unroll
    for (int k=0;k<9;k++){ wv0[k] = wp0[k]; wv1[k] = wp0[9+k]; }
    uint32_t* ob = out + ((size_t)b*LL + (size_t)y*Wd + x0)*Cw + cw;
#pragma unroll
    for (int xo=0; xo<4; xo++){
        float a0 = 0.f, a1 = 0.f;
#pragma unroll
        for (int ky=0;ky<3;ky++)
#pragma unroll
            for (int kx=0;kx<3;kx++){
                a0 += r0[ky][xo+kx]*wv0[ky*3+kx];
                a1 += r1[ky][xo+kx]*wv1[ky*3+kx];
            }
        if (doGelu){ a0 = gelu_f(a0); a1 = gelu_f(a1); }
        ob[(size_t)xo*Cw] = packbf(a0, a1);
    }
}

// ---------------- deterministic pooling + channel gate ----------------
__global__ void pool_partial(const __nv_bfloat16* __restrict__ conv, float* __restrict__ pp){
    int b = blockIdx.y, chunk = blockIdx.x, c = threadIdx.x;
    const __nv_bfloat16* p = conv + ((size_t)b*LL + (size_t)chunk*128)*Cc + c;
    float s=0.f;
    for (int r=0;r<128;r++) s += __bfloat162float(p[(size_t)r*Cc]);
    pp[(b*128+chunk)*Cc + c] = s;
}

__global__ void pool_final_cm(const float* __restrict__ pp, const float* __restrict__ w1,
                              const float* __restrict__ w2, float* __restrict__ cm){
    int b = blockIdx.x, c = threadIdx.x;
    __shared__ float ps[Cc];
    __shared__ float ts[REDc];
    float s=0.f;
    for (int r=0;r<128;r++) s += pp[(b*128+r)*Cc + c];
    ps[c] = s*(1.f/(float)LL);
    __syncthreads();
    if (c < REDc){
        float t=0.f;
        for (int j=0;j<Cc;j++) t += ps[j]*w1[c*Cc+j];
        ts[c] = gelu_f(t);
    }
    __syncthreads();
    float a=0.f;
#pragma unroll
    for (int r=0;r<REDc;r++) a += ts[r]*w2[c*REDc+r];
    cm[b*Cc+c] = 1.f/(1.f+__expf(-a));
}

// ---------------- residual + LN2 fused ----------------
__global__ void resid_ln2_kernel(const float* __restrict__ x, const uint32_t* __restrict__ attn,
    const uint32_t* __restrict__ conv, const float* __restrict__ cm,
    const float* __restrict__ w, const float* __restrict__ bb,
    float* __restrict__ xmid, uint32_t* __restrict__ n2){
    int warp = (blockIdx.x*blockDim.x + threadIdx.x) >> 5;
    int lane = threadIdx.x & 31;
    if (warp >= TOK) return;
    int b = warp / LL;
    size_t base = (size_t)warp*Cc;
    float v[3][2]; float s=0.f;
#pragma unroll
    for (int k=0;k<3;k++){
        int c2 = lane+32*k;
        int c = 2*c2;
        float2 xv = *(const float2*)&x[base+c];
        float2 av = unpackbf(attn[(size_t)warp*96 + c2]);
        float2 cv = unpackbf(conv[(size_t)warp*96 + c2]);
        float2 gv = *(const float2*)&cm[b*Cc+c];
        float m0 = xv.x + av.x*gv.x + cv.x;
        float m1 = xv.y + av.y*gv.y + cv.y;
        float2 o; o.x=m0; o.y=m1;
        *(float2*)&xmid[base+c] = o;
        v[k][0]=m0; v[k][1]=m1; s+=m0+m1;
    }
#pragma unroll
    for (int o=16;o;o>>=1) s += __shfl_xor_sync(0xffffffffu, s, o);
    float mean = s*(1.f/192.f);
    float q = 0.f;
#pragma unroll
    for (int k=0;k<3;k++){ float d0=v[k][0]-mean, d1=v[k][1]-mean; q += d0*d0 + d1*d1; }
#pragma unroll
    for (int o=16;o;o>>=1) q += __shfl_xor_sync(0xffffffffu, q, o);
    float inv = rsqrtf(q*(1.f/192.f)+1e-5f);
    uint32_t* op = n2 + (size_t)warp*96;
#pragma unroll
    for (int k=0;k<3;k++){
        int c2 = lane+32*k;
        float r0 = (v[k][0]-mean)*inv*w[2*c2]+bb[2*c2];
        float r1 = (v[k][1]-mean)*inv*w[2*c2+1]+bb[2*c2+1];
        op[c2] = packbf(r0, r1);
    }
}

// ---------------- launch (multi-stream fork/join, graph-capturable) ----------------
extern "C" void kernel_launch(void* const* d_in, const int* in_sizes, int n_in,
                              void* d_out, int out_size){
    const float* x     = (const float*)d_in[0];
    const float* n1w   = (const float*)d_in[3];
    const float* n1b   = (const float*)d_in[4];
    const float* qkvw  = (const float*)d_in[5];
    const float* projw = (const float*)d_in[6];
    const float* projb = (const float*)d_in[7];
    const float* abias = (const float*)d_in[8];
    const float* convw = (const float*)d_in[9];
    const float* cgw1  = (const float*)d_in[10];
    const float* cgw2  = (const float*)d_in[11];
    const float* n2w   = (const float*)d_in[12];
    const float* n2b   = (const float*)d_in[13];
    const float* fc1w  = (const float*)d_in[14];
    const float* smixw = (const float*)d_in[15];
    const float* fc2w  = (const float*)d_in[16];
    float* out = (float*)d_out;

    uint32_t *n1p, *aop, *qkvp, *hp, *h2p, *wtp, *attnp, *convp;
    float *ppp, *cmp;
    cudaGetSymbolAddress((void**)&n1p,   g_n1);
    cudaGetSymbolAddress((void**)&aop,   g_ao);
    cudaGetSymbolAddress((void**)&qkvp,  g_qkv);
    cudaGetSymbolAddress((void**)&hp,    g_h);
    cudaGetSymbolAddress((void**)&h2p,   g_h2);
    cudaGetSymbolAddress((void**)&wtp,   g_wt);
    cudaGetSymbolAddress((void**)&attnp, g_attn);
    cudaGetSymbolAddress((void**)&convp, g_conv);
    cudaGetSymbolAddress((void**)&ppp,   g_poolp);
    cudaGetSymbolAddress((void**)&cmp,   g_cm);

    cudaFuncSetAttribute(gemm_mma, cudaFuncAttributeMaxDynamicSharedMemorySize, GEMM_SMEM);

    static cudaStream_t s1 = nullptr;
    static cudaEvent_t evRoot = nullptr, evT = nullptr, evLN = nullptr, evCM = nullptr;
    if (s1 == nullptr){
        cudaStreamCreateWithFlags(&s1, cudaStreamNonBlocking);
        cudaEventCreateWithFlags(&evRoot, cudaEventDisableTiming);
        cudaEventCreateWithFlags(&evT,    cudaEventDisableTiming);
        cudaEventCreateWithFlags(&evLN,   cudaEventDisableTiming);
        cudaEventCreateWithFlags(&evCM,   cudaEventDisableTiming);
    }

    cudaEventRecord(evRoot, 0);
    cudaStreamWaitEvent(s1, evRoot, 0);

    transpose_all<<<576, 256, 0, s1>>>(qkvw, projw, fc1w, fc2w, wtp);
    cudaEventRecord(evT, s1);

    ln_kernel<<<TOK/8, 256>>>(x, n1w, n1b, n1p);
    cudaEventRecord(evLN, 0);

    cudaStreamWaitEvent(s1, evLN, 0);
    dwconv4w<<<(TOK*96/4 + 255)/256, 256, 0, s1>>>(n1p, convw, convp, 96, 1);
    pool_partial<<<dim3(128, Bsz), Cc, 0, s1>>>((const __nv_bfloat16*)convp, ppp);
    pool_final_cm<<<Bsz, Cc, 0, s1>>>(ppp, cgw1, cgw2, cmp);
    cudaEventRecord(evCM, s1);

    cudaStreamWaitEvent(0, evT, 0);
    gemm_mma<<<dim3(QKVN/64, TOK/256), 256, GEMM_SMEM>>>(n1p, wtp+WTB_QKV, qkvp, nullptr, QKVN, Cc, 7);
    attn_mma<<<dim3(2048, 3), 256>>>(qkvp, abias, aop);
    gemm_mma<<<dim3(Cc/64, TOK/256), 256, GEMM_SMEM>>>(aop, wtp+WTB_PROJ, attnp, projb, Cc, Cc, 6);

    cudaStreamWaitEvent(0, evCM, 0);
    resid_ln2_kernel<<<TOK/8, 256>>>(x, attnp, convp, cmp, n2w, n2b, out, n1p);
    gemm_mma<<<dim3(HDIMc/64, TOK/256), 256, GEMM_SMEM>>>(n1p, wtp+WTB_FC1, hp, nullptr, HDIMc, Cc, 5);
    dwconv4w<<<(TOK*192/4 + 255)/256, 256>>>(hp, smixw, h2p, 192, 0);
    gemm_mma<<<dim3(Cc/64, TOK/256), 256, GEMM_SMEM>>>(h2p, wtp+WTB_FC2, out, out, Cc, HDIMc, 3);
}